// round 16
// baseline (speedup 1.0000x reference)
#include <cuda_runtime.h>

// ---------------------------------------------------------------------------
// Sparse masked 3D U-Net (presetUResNet) on 96^3 grid, fp32.
// R15 = R10 byte-exact conv bodies (sorted lists + channel-major + voxel-pair
// x 8-cout conv3), plus:
//  * __launch_bounds__(256, 5) on the <=32-input-channel conv3 instantiations
//    (48-reg cap -> 5 blocks/SM -> 40 warps/SM, +25% latency hiding)
//  * int2 paired list loads
//  * exact worst-case grids for level-2 convs
//  * max-L1 carveout on conv kernels
// ---------------------------------------------------------------------------

constexpr int D0 = 96, D1 = 48, D2 = 24;
constexpr int V0 = D0 * D0 * D0;   // 884736
constexpr int V1 = D1 * D1 * D1;   // 110592
constexpr int V2 = D2 * D2 * D2;   // 13824

// ---- scratch arena layout (floats), feature buffers channel-major [c][v] ----
constexpr int OFF_XM    = 0;
constexpr int OFF_SKIP0 = OFF_XM    + V0;
constexpr int OFF_UP1   = OFF_SKIP0 + 16 * V0;
constexpr int OFF_T32   = OFF_UP1   + 16 * V0;
constexpr int OFF_HA    = OFF_T32   + 32 * V0;
constexpr int OFF_HB    = OFF_HA    + 32 * V1;
constexpr int OFF_S1    = OFF_HB    + 32 * V1;
constexpr int OFF_H64   = OFF_S1    + 32 * V1;
constexpr int OFF_CA    = OFF_H64   + 64 * V1;
constexpr int OFF_CB    = OFF_CA    + 64 * V2;
constexpr int FEAT_END  = OFF_CB    + 64 * V2;
constexpr int OFF_M1    = FEAT_END;
constexpr int OFF_M2    = OFF_M1 + V1;
constexpr int OFF_W     = OFF_M2 + V2;
// transposed weights: layout [(ci*K3 + t)*Copad + o]
constexpr int WO_IN  = OFF_W;
constexpr int WO_E0D = WO_IN  + 1  * 27 * 16;
constexpr int WO_E0A = WO_E0D + 16 * 8  * 32;
constexpr int WO_E0B = WO_E0A + 32 * 27 * 32;
constexpr int WO_E1D = WO_E0B + 32 * 27 * 32;
constexpr int WO_E1A = WO_E1D + 32 * 8  * 64;
constexpr int WO_E1B = WO_E1A + 64 * 27 * 64;
constexpr int WO_D0U = WO_E1B + 64 * 27 * 64;
constexpr int WO_D0A = WO_D0U + 64 * 8  * 32;
constexpr int WO_D0B = WO_D0A + 64 * 27 * 64;
constexpr int WO_D1U = WO_D0B + 64 * 27 * 32;
constexpr int WO_D1A = WO_D1U + 32 * 8  * 16;
constexpr int WO_D1B = WO_D1A + 32 * 27 * 32;
constexpr int WO_OA  = WO_D1B + 32 * 27 * 16;
constexpr int WO_OB  = WO_OA  + 16 * 27 * 16;
constexpr int SCRATCH_TOTAL = WO_OB + 16 * 27 * 8;

// sorted-list build: 1024-voxel chunks
constexpr int CH0 = (V0 + 1023) / 1024;
constexpr int CH1 = (V1 + 1023) / 1024;
constexpr int CH2 = (V2 + 1023) / 1024;
constexpr int CHT = CH0 + CH1 + CH2;

__device__ __align__(256) float g_scratch[SCRATCH_TOTAL];  // zero-initialized
__device__ __align__(8) int g_list0[V0];
__device__ __align__(8) int g_list1[V1];
__device__ __align__(8) int g_list2[V2];
__device__ int g_cnt[4];
__device__ int g_chunkcnt[CHT];
__device__ int g_chunkoff[CHT];

// ---------------------------------------------------------------------------
// prep kernels (identical to R10)
// ---------------------------------------------------------------------------

__global__ void prep1_kernel(const float* __restrict__ x,
                             const float* __restrict__ occ,
                             float* __restrict__ out, int outn) {
    int stride = gridDim.x * blockDim.x;
    int gt = blockIdx.x * blockDim.x + threadIdx.x;
    float4 z4 = make_float4(0.f, 0.f, 0.f, 0.f);
    float4* o4 = reinterpret_cast<float4*>(out);
    for (int i = gt; i < outn / 4; i += stride) o4[i] = z4;
    for (int i = gt; i < V0; i += stride) g_scratch[OFF_XM + i] = x[i] * occ[i];
    for (int i = gt; i < V1; i += stride) {
        int xx = i % D1, yy = (i / D1) % D1, zz = i / (D1 * D1);
        float m = 0.f;
        #pragma unroll
        for (int dz = 0; dz < 2; dz++)
            #pragma unroll
            for (int dy = 0; dy < 2; dy++)
                #pragma unroll
                for (int dx = 0; dx < 2; dx++)
                    m = fmaxf(m, occ[((2 * zz + dz) * D0 + 2 * yy + dy) * D0 + 2 * xx + dx]);
        g_scratch[OFF_M1 + i] = m;
    }
    for (int i = gt; i < V2; i += stride) {
        int xx = i % D2, yy = (i / D2) % D2, zz = i / (D2 * D2);
        float m = 0.f;
        for (int dz = 0; dz < 4; dz++)
            for (int dy = 0; dy < 4; dy++)
                #pragma unroll
                for (int dx = 0; dx < 4; dx++)
                    m = fmaxf(m, occ[((4 * zz + dz) * D0 + 4 * yy + dy) * D0 + 4 * xx + dx]);
        g_scratch[OFF_M2 + i] = m;
    }
    for (int i = gt; i < CHT; i += stride) g_chunkcnt[i] = 0;
}

__global__ void count_kernel(const float* __restrict__ occ) {
    const float* mask; int n, cbase;
    if (blockIdx.y == 0)      { mask = occ;                n = V0; cbase = 0; }
    else if (blockIdx.y == 1) { mask = g_scratch + OFF_M1; n = V1; cbase = CH0; }
    else                      { mask = g_scratch + OFF_M2; n = V2; cbase = CH0 + CH1; }
    int chunk = blockIdx.x;
    long base = (long)chunk * 1024;
    if (base >= n) return;
    int cnt = 0;
    #pragma unroll
    for (int r = 0; r < 4; r++) {
        long i = base + r * 256 + threadIdx.x;
        if (i < n && mask[i] > 0.5f) cnt++;
    }
    #pragma unroll
    for (int s = 16; s > 0; s >>= 1) cnt += __shfl_down_sync(0xffffffffu, cnt, s);
    if ((threadIdx.x & 31) == 0 && cnt) atomicAdd(&g_chunkcnt[cbase + chunk], cnt);
}

__global__ void scan_kernel() {
    __shared__ int s[1024];
    int t = threadIdx.x;
    int segBase[3] = {0, CH0, CH0 + CH1};
    int segCnt[3]  = {CH0, CH1, CH2};
    for (int seg = 0; seg < 3; seg++) {
        int val = (t < segCnt[seg]) ? g_chunkcnt[segBase[seg] + t] : 0;
        s[t] = val;
        __syncthreads();
        for (int d = 1; d < 1024; d <<= 1) {
            int add = (t >= d) ? s[t - d] : 0;
            __syncthreads();
            s[t] += add;
            __syncthreads();
        }
        if (t < segCnt[seg]) g_chunkoff[segBase[seg] + t] = s[t] - val;
        if (t == segCnt[seg] - 1) g_cnt[seg] = s[t];
        __syncthreads();
    }
}

__global__ void scatter_kernel(const float* __restrict__ occ) {
    const float* mask; int n, cbase; int* list;
    if (blockIdx.y == 0)      { mask = occ;                n = V0; cbase = 0;        list = g_list0; }
    else if (blockIdx.y == 1) { mask = g_scratch + OFF_M1; n = V1; cbase = CH0;      list = g_list1; }
    else                      { mask = g_scratch + OFF_M2; n = V2; cbase = CH0+CH1;  list = g_list2; }
    int chunk = blockIdx.x;
    long cb = (long)chunk * 1024;
    if (cb >= n) return;
    int lane = threadIdx.x & 31;
    int base = g_chunkoff[cbase + chunk];
    for (int r = 0; r < 32; r++) {
        long i = cb + r * 32 + lane;
        bool pred = (i < n) && (mask[i] > 0.5f);
        unsigned bal = __ballot_sync(0xffffffffu, pred);
        if (pred) list[base + __popc(bal & ((1u << lane) - 1))] = (int)i;
        base += __popc(bal);
    }
}

struct WPtrs { const float* p[15]; };
__device__ const int TW_DIMS[15][4] = {
    {16, 1, 27, 16}, {32, 16, 8, 32}, {32, 32, 27, 32}, {32, 32, 27, 32},
    {64, 32, 8, 64}, {64, 64, 27, 64}, {64, 64, 27, 64}, {32, 64, 8, 32},
    {64, 64, 27, 64}, {32, 64, 27, 32}, {16, 32, 8, 16}, {32, 32, 27, 32},
    {16, 32, 27, 16}, {16, 16, 27, 16}, {5, 16, 27, 8}};
__device__ const int TW_OFF[15] = {
    WO_IN, WO_E0D, WO_E0A, WO_E0B, WO_E1D, WO_E1A, WO_E1B, WO_D0U,
    WO_D0A, WO_D0B, WO_D1U, WO_D1A, WO_D1B, WO_OA, WO_OB};

__global__ void tw_kernel(WPtrs wp) {
    int e = blockIdx.y;
    int Cout = TW_DIMS[e][0], Cin = TW_DIMS[e][1], K3 = TW_DIMS[e][2], Copad = TW_DIMS[e][3];
    const float* w = wp.p[e];
    float* wt = g_scratch + TW_OFF[e];
    int total = Cin * K3 * Copad;
    for (int i = blockIdx.x * blockDim.x + threadIdx.x; i < total;
         i += gridDim.x * blockDim.x) {
        int o = i % Copad;
        int r = i / Copad;
        int ci = r / K3, t = r % K3;
        wt[i] = (o < Cout) ? w[(o * Cin + ci) * K3 + t] : 0.f;
    }
}

// ---------------------------------------------------------------------------
// conv3: voxel-pair x 8-cout gather conv (R10 body; MINB = min blocks/SM)
// ---------------------------------------------------------------------------

template <int CINA, int CINB, int COUT, int COPAD, bool RELU, int MINB>
__global__ __launch_bounds__(256, MINB)
void conv3_pair8(const float* __restrict__ inA, const float* __restrict__ inB,
                 const float* __restrict__ wt, float* __restrict__ out,
                 const int* __restrict__ list, const int* __restrict__ cnt,
                 int cntIdx, int D) {
    const int vol = D * D * D;
    const int CG = COPAD / 8;
    int n = cnt[cntIdx];
    int npair = (n + 1) >> 1;
    int total = npair * CG;
    for (int w = blockIdx.x * blockDim.x + threadIdx.x; w < total;
         w += gridDim.x * blockDim.x) {
        int pi = w / CG;
        int cg = w % CG;
        int i0 = 2 * pi;
        bool has1 = (i0 + 1) < n;
        int2 vp = *reinterpret_cast<const int2*>(list + i0);
        int v0 = vp.x;
        int v1 = has1 ? vp.y : v0;
        int x0 = v0 % D, y0 = (v0 / D) % D, z0 = v0 / (D * D);
        int x1 = v1 % D, y1 = (v1 / D) % D, z1 = v1 / (D * D);
        float4 a0 = make_float4(0.f, 0.f, 0.f, 0.f);
        float4 a0h = make_float4(0.f, 0.f, 0.f, 0.f);
        float4 a1 = make_float4(0.f, 0.f, 0.f, 0.f);
        float4 a1h = make_float4(0.f, 0.f, 0.f, 0.f);
        for (int dz = -1; dz <= 1; dz++) {
            int zz0 = z0 + dz, zz1 = z1 + dz;
            bool zk0 = (unsigned)zz0 < (unsigned)D;
            bool zk1 = (unsigned)zz1 < (unsigned)D;
            if (!zk0 && !zk1) continue;
            for (int dy = -1; dy <= 1; dy++) {
                int yy0 = y0 + dy, yy1 = y1 + dy;
                bool yk0 = zk0 && ((unsigned)yy0 < (unsigned)D);
                bool yk1 = zk1 && ((unsigned)yy1 < (unsigned)D);
                if (!yk0 && !yk1) continue;
                for (int dx = -1; dx <= 1; dx++) {
                    int xx0 = x0 + dx, xx1 = x1 + dx;
                    bool k0 = yk0 && ((unsigned)xx0 < (unsigned)D);
                    bool k1 = yk1 && ((unsigned)xx1 < (unsigned)D);
                    if (!k0 && !k1) continue;
                    int t = ((dz + 1) * 3 + (dy + 1)) * 3 + (dx + 1);
                    int noff0 = k0 ? (zz0 * D + yy0) * D + xx0 : 0;
                    int noff1 = k1 ? (zz1 * D + yy1) * D + xx1 : 0;
                    const float* ip0 = inA + noff0;
                    const float* ip1 = inA + noff1;
                    const float* wp = wt + t * COPAD + cg * 8;
                    #pragma unroll
                    for (int ci = 0; ci < CINA; ci++) {
                        float a = k0 ? __ldg(ip0) : 0.f; ip0 += vol;
                        float b = k1 ? __ldg(ip1) : 0.f; ip1 += vol;
                        float4 wl = *reinterpret_cast<const float4*>(wp);
                        float4 wh = *reinterpret_cast<const float4*>(wp + 4);
                        wp += 27 * COPAD;
                        a0.x += a * wl.x; a0.y += a * wl.y;
                        a0.z += a * wl.z; a0.w += a * wl.w;
                        a0h.x += a * wh.x; a0h.y += a * wh.y;
                        a0h.z += a * wh.z; a0h.w += a * wh.w;
                        a1.x += b * wl.x; a1.y += b * wl.y;
                        a1.z += b * wl.z; a1.w += b * wl.w;
                        a1h.x += b * wh.x; a1h.y += b * wh.y;
                        a1h.z += b * wh.z; a1h.w += b * wh.w;
                    }
                    if (CINB > 0) {
                        const float* jp0 = inB + noff0;
                        const float* jp1 = inB + noff1;
                        #pragma unroll
                        for (int ci = 0; ci < CINB; ci++) {
                            float a = k0 ? __ldg(jp0) : 0.f; jp0 += vol;
                            float b = k1 ? __ldg(jp1) : 0.f; jp1 += vol;
                            float4 wl = *reinterpret_cast<const float4*>(wp);
                            float4 wh = *reinterpret_cast<const float4*>(wp + 4);
                            wp += 27 * COPAD;
                            a0.x += a * wl.x; a0.y += a * wl.y;
                            a0.z += a * wl.z; a0.w += a * wl.w;
                            a0h.x += a * wh.x; a0h.y += a * wh.y;
                            a0h.z += a * wh.z; a0h.w += a * wh.w;
                            a1.x += b * wl.x; a1.y += b * wl.y;
                            a1.z += b * wl.z; a1.w += b * wl.w;
                            a1h.x += b * wh.x; a1h.y += b * wh.y;
                            a1h.z += b * wh.z; a1h.w += b * wh.w;
                        }
                    }
                }
            }
        }
        if (RELU) {
            a0.x = fmaxf(a0.x, 0.f); a0.y = fmaxf(a0.y, 0.f);
            a0.z = fmaxf(a0.z, 0.f); a0.w = fmaxf(a0.w, 0.f);
            a0h.x = fmaxf(a0h.x, 0.f); a0h.y = fmaxf(a0h.y, 0.f);
            a0h.z = fmaxf(a0h.z, 0.f); a0h.w = fmaxf(a0h.w, 0.f);
            a1.x = fmaxf(a1.x, 0.f); a1.y = fmaxf(a1.y, 0.f);
            a1.z = fmaxf(a1.z, 0.f); a1.w = fmaxf(a1.w, 0.f);
            a1h.x = fmaxf(a1h.x, 0.f); a1h.y = fmaxf(a1h.y, 0.f);
            a1h.z = fmaxf(a1h.z, 0.f); a1h.w = fmaxf(a1h.w, 0.f);
        }
        int co = cg * 8;
        float r0[8] = {a0.x, a0.y, a0.z, a0.w, a0h.x, a0h.y, a0h.z, a0h.w};
        float r1[8] = {a1.x, a1.y, a1.z, a1.w, a1h.x, a1h.y, a1h.z, a1h.w};
        #pragma unroll
        for (int k = 0; k < 8; k++)
            if (co + k < COUT) out[(co + k) * vol + v0] = r0[k];
        if (has1) {
            #pragma unroll
            for (int k = 0; k < 8; k++)
                if (co + k < COUT) out[(co + k) * vol + v1] = r1[k];
        }
    }
}

// ---------------------------------------------------------------------------
// down2: voxel-pair tiling (unchanged from R10)
// ---------------------------------------------------------------------------

template <int CIN, int COUT, int COPAD>
__global__ __launch_bounds__(256)
void down2_pair(const float* __restrict__ in, const float* __restrict__ wt,
                float* __restrict__ out, const int* __restrict__ list,
                const int* __restrict__ cnt, int cntIdx, int Dc) {
    const int Df = Dc * 2;
    const int volf = Df * Df * Df;
    const int volc = Dc * Dc * Dc;
    const int CG = COPAD / 4;
    int n = cnt[cntIdx];
    int npair = (n + 1) >> 1;
    int total = npair * CG;
    for (int w = blockIdx.x * blockDim.x + threadIdx.x; w < total;
         w += gridDim.x * blockDim.x) {
        int pi = w / CG;
        int cg = w % CG;
        int i0 = 2 * pi;
        bool has1 = (i0 + 1) < n;
        int2 vp = *reinterpret_cast<const int2*>(list + i0);
        int v0 = vp.x;
        int v1 = has1 ? vp.y : v0;
        int x0 = v0 % Dc, y0 = (v0 / Dc) % Dc, z0 = v0 / (Dc * Dc);
        int x1 = v1 % Dc, y1 = (v1 / Dc) % Dc, z1 = v1 / (Dc * Dc);
        float4 acc0 = make_float4(0.f, 0.f, 0.f, 0.f);
        float4 acc1 = make_float4(0.f, 0.f, 0.f, 0.f);
        #pragma unroll
        for (int t = 0; t < 8; t++) {
            int tz = t >> 2, ty = (t >> 1) & 1, tx = t & 1;
            int noff0 = ((2 * z0 + tz) * Df + (2 * y0 + ty)) * Df + (2 * x0 + tx);
            int noff1 = ((2 * z1 + tz) * Df + (2 * y1 + ty)) * Df + (2 * x1 + tx);
            const float* ip0 = in + noff0;
            const float* ip1 = in + noff1;
            const float* wp = wt + t * COPAD + cg * 4;
            #pragma unroll
            for (int ci = 0; ci < CIN; ci++) {
                float a = __ldg(ip0); ip0 += volf;
                float b = __ldg(ip1); ip1 += volf;
                float4 wv = *reinterpret_cast<const float4*>(wp);
                wp += 8 * COPAD;
                acc0.x += a * wv.x; acc0.y += a * wv.y;
                acc0.z += a * wv.z; acc0.w += a * wv.w;
                acc1.x += b * wv.x; acc1.y += b * wv.y;
                acc1.z += b * wv.z; acc1.w += b * wv.w;
            }
        }
        int co = cg * 4;
        out[(co + 0) * volc + v0] = acc0.x;
        out[(co + 1) * volc + v0] = acc0.y;
        out[(co + 2) * volc + v0] = acc0.z;
        out[(co + 3) * volc + v0] = acc0.w;
        if (has1) {
            out[(co + 0) * volc + v1] = acc1.x;
            out[(co + 1) * volc + v1] = acc1.y;
            out[(co + 2) * volc + v1] = acc1.z;
            out[(co + 3) * volc + v1] = acc1.w;
        }
    }
}

// ---------------------------------------------------------------------------
// up2 (unchanged)
// ---------------------------------------------------------------------------

template <int CIN, int COUT, int COPAD>
__global__ __launch_bounds__(256)
void up2_kernel(const float* __restrict__ in, const float* __restrict__ wt,
                float* __restrict__ out, const int* __restrict__ list,
                const int* __restrict__ cnt, int cntIdx, int Df) {
    const int Dc = Df / 2;
    const int volf = Df * Df * Df;
    const int volc = Dc * Dc * Dc;
    const int CG = COPAD / 4;
    int n = cnt[cntIdx];
    int total = n * CG;
    for (int w = blockIdx.x * blockDim.x + threadIdx.x; w < total;
         w += gridDim.x * blockDim.x) {
        int v = list[w / CG];
        int cg = w % CG;
        int x0 = v % Df, y0 = (v / Df) % Df, z0 = v / (Df * Df);
        int t = ((1 - (z0 & 1)) * 2 + (1 - (y0 & 1))) * 2 + (1 - (x0 & 1));
        int coff = ((z0 >> 1) * Dc + (y0 >> 1)) * Dc + (x0 >> 1);
        float4 acc = make_float4(0.f, 0.f, 0.f, 0.f);
        const float* ip = in + coff;
        const float* wp = wt + t * COPAD + cg * 4;
        #pragma unroll
        for (int ci = 0; ci < CIN; ci++) {
            float iv = __ldg(ip); ip += volc;
            float4 wv = *reinterpret_cast<const float4*>(wp);
            wp += 8 * COPAD;
            acc.x += iv * wv.x; acc.y += iv * wv.y;
            acc.z += iv * wv.z; acc.w += iv * wv.w;
        }
        int co = cg * 4;
        out[(co + 0) * volf + v] = acc.x;
        out[(co + 1) * volf + v] = acc.y;
        out[(co + 2) * volf + v] = acc.z;
        out[(co + 3) * volf + v] = acc.w;
    }
}

// ---------------------------------------------------------------------------
// launch
// ---------------------------------------------------------------------------

extern "C" void kernel_launch(void* const* d_in, const int* in_sizes, int n_in,
                              void* d_out, int out_size) {
    (void)in_sizes; (void)n_in;
    const float* x   = (const float*)d_in[0];
    const float* occ = (const float*)d_in[1];
    float* out = (float*)d_out;

    float* SB = nullptr;
    int *L0 = nullptr, *L1 = nullptr, *L2 = nullptr, *CNT = nullptr;
    cudaGetSymbolAddress((void**)&SB,  g_scratch);
    cudaGetSymbolAddress((void**)&L0,  g_list0);
    cudaGetSymbolAddress((void**)&L1,  g_list1);
    cudaGetSymbolAddress((void**)&L2,  g_list2);
    cudaGetSymbolAddress((void**)&CNT, g_cnt);

    const int NT = 256;
    const int NB = 2048;

    // max-L1 carveout for the heavy conv instantiations (no smem used)
    static bool attrs_set = false;
    if (!attrs_set) {
        attrs_set = true;
        cudaFuncSetAttribute(conv3_pair8<32, 0, 32, 32, true, 5>,
                             cudaFuncAttributePreferredSharedMemoryCarveout, 0);
        cudaFuncSetAttribute(conv3_pair8<32, 0, 32, 32, false, 5>,
                             cudaFuncAttributePreferredSharedMemoryCarveout, 0);
        cudaFuncSetAttribute(conv3_pair8<64, 0, 64, 64, true, 4>,
                             cudaFuncAttributePreferredSharedMemoryCarveout, 0);
        cudaFuncSetAttribute(conv3_pair8<64, 0, 64, 64, false, 4>,
                             cudaFuncAttributePreferredSharedMemoryCarveout, 0);
        cudaFuncSetAttribute(conv3_pair8<32, 32, 64, 64, true, 4>,
                             cudaFuncAttributePreferredSharedMemoryCarveout, 0);
        cudaFuncSetAttribute(conv3_pair8<64, 0, 32, 32, false, 4>,
                             cudaFuncAttributePreferredSharedMemoryCarveout, 0);
        cudaFuncSetAttribute(conv3_pair8<16, 16, 32, 32, true, 5>,
                             cudaFuncAttributePreferredSharedMemoryCarveout, 0);
        cudaFuncSetAttribute(conv3_pair8<32, 0, 16, 16, false, 5>,
                             cudaFuncAttributePreferredSharedMemoryCarveout, 0);
        cudaFuncSetAttribute(conv3_pair8<16, 0, 16, 16, true, 5>,
                             cudaFuncAttributePreferredSharedMemoryCarveout, 0);
        cudaFuncSetAttribute(conv3_pair8<16, 0, 5, 8, false, 5>,
                             cudaFuncAttributePreferredSharedMemoryCarveout, 0);
    }

    prep1_kernel<<<1024, NT>>>(x, occ, out, out_size);
    count_kernel<<<dim3(CH0, 3), NT>>>(occ);
    scan_kernel<<<1, 1024>>>();
    scatter_kernel<<<dim3(CH0, 3), 32>>>(occ);
    WPtrs wp;
    for (int i = 0; i < 15; i++) wp.p[i] = (const float*)d_in[2 + i];
    tw_kernel<<<dim3(216, 15), NT>>>(wp);

    // U-Net pipeline (channel-major features)
    conv3_pair8<1, 0, 16, 16, false, 5><<<NB, NT>>>(
        SB + OFF_XM, nullptr, SB + WO_IN, SB + OFF_SKIP0, L0, CNT, 0, D0);

    // encoder level 0
    down2_pair<16, 32, 32><<<NB, NT>>>(
        SB + OFF_SKIP0, SB + WO_E0D, SB + OFF_HA, L1, CNT, 1, D1);
    conv3_pair8<32, 0, 32, 32, true, 5><<<NB, NT>>>(
        SB + OFF_HA, nullptr, SB + WO_E0A, SB + OFF_HB, L1, CNT, 1, D1);
    conv3_pair8<32, 0, 32, 32, false, 5><<<NB, NT>>>(
        SB + OFF_HB, nullptr, SB + WO_E0B, SB + OFF_S1, L1, CNT, 1, D1);

    // encoder level 1 (exact worst-case grids at level 2: V2 bound is tight)
    down2_pair<32, 64, 64><<<432, NT>>>(
        SB + OFF_S1, SB + WO_E1D, SB + OFF_CA, L2, CNT, 2, D2);
    conv3_pair8<64, 0, 64, 64, true, 4><<<216, NT>>>(
        SB + OFF_CA, nullptr, SB + WO_E1A, SB + OFF_CB, L2, CNT, 2, D2);
    conv3_pair8<64, 0, 64, 64, false, 4><<<216, NT>>>(
        SB + OFF_CB, nullptr, SB + WO_E1B, SB + OFF_CA, L2, CNT, 2, D2);

    // decoder stage 0 (to level 1)
    up2_kernel<64, 32, 32><<<NB, NT>>>(
        SB + OFF_CA, SB + WO_D0U, SB + OFF_HA, L1, CNT, 1, D1);
    conv3_pair8<32, 32, 64, 64, true, 4><<<NB, NT>>>(
        SB + OFF_HA, SB + OFF_S1, SB + WO_D0A, SB + OFF_H64, L1, CNT, 1, D1);
    conv3_pair8<64, 0, 32, 32, false, 4><<<NB, NT>>>(
        SB + OFF_H64, nullptr, SB + WO_D0B, SB + OFF_HB, L1, CNT, 1, D1);

    // decoder stage 1 (to level 0)
    up2_kernel<32, 16, 16><<<NB, NT>>>(
        SB + OFF_HB, SB + WO_D1U, SB + OFF_UP1, L0, CNT, 0, D0);
    conv3_pair8<16, 16, 32, 32, true, 5><<<NB, NT>>>(
        SB + OFF_UP1, SB + OFF_SKIP0, SB + WO_D1A, SB + OFF_T32, L0, CNT, 0, D0);
    conv3_pair8<32, 0, 16, 16, false, 5><<<NB, NT>>>(
        SB + OFF_T32, nullptr, SB + WO_D1B, SB + OFF_UP1, L0, CNT, 0, D0);

    // output block
    conv3_pair8<16, 0, 16, 16, true, 5><<<NB, NT>>>(
        SB + OFF_UP1, nullptr, SB + WO_OA, SB + OFF_SKIP0, L0, CNT, 0, D0);
    conv3_pair8<16, 0, 5, 8, false, 5><<<NB, NT>>>(
        SB + OFF_SKIP0, nullptr, SB + WO_OB, out, L0, CNT, 0, D0);
}

// round 17
// speedup vs baseline: 1.0672x; 1.0672x over previous
#include <cuda_runtime.h>

// ---------------------------------------------------------------------------
// Sparse masked 3D U-Net (presetUResNet) on 96^3 grid, fp32.
// R16 = R10 (sorted lists + channel-major + voxel-pair x 8-cout conv3, the
// validated optimum) with ONE change inside the conv3 inner loop:
// ci-chunked load batching — 8 input LDGs issued back-to-back per chunk of 4
// input channels (MLP 2 -> 8 on the L2-latency path), then the FMA blocks.
// FMA order per accumulator unchanged -> bit-identical results.
// ---------------------------------------------------------------------------

constexpr int D0 = 96, D1 = 48, D2 = 24;
constexpr int V0 = D0 * D0 * D0;   // 884736
constexpr int V1 = D1 * D1 * D1;   // 110592
constexpr int V2 = D2 * D2 * D2;   // 13824

// ---- scratch arena layout (floats), feature buffers channel-major [c][v] ----
constexpr int OFF_XM    = 0;
constexpr int OFF_SKIP0 = OFF_XM    + V0;
constexpr int OFF_UP1   = OFF_SKIP0 + 16 * V0;
constexpr int OFF_T32   = OFF_UP1   + 16 * V0;
constexpr int OFF_HA    = OFF_T32   + 32 * V0;
constexpr int OFF_HB    = OFF_HA    + 32 * V1;
constexpr int OFF_S1    = OFF_HB    + 32 * V1;
constexpr int OFF_H64   = OFF_S1    + 32 * V1;
constexpr int OFF_CA    = OFF_H64   + 64 * V1;
constexpr int OFF_CB    = OFF_CA    + 64 * V2;
constexpr int FEAT_END  = OFF_CB    + 64 * V2;
constexpr int OFF_M1    = FEAT_END;
constexpr int OFF_M2    = OFF_M1 + V1;
constexpr int OFF_W     = OFF_M2 + V2;
// transposed weights: layout [(ci*K3 + t)*Copad + o]
constexpr int WO_IN  = OFF_W;
constexpr int WO_E0D = WO_IN  + 1  * 27 * 16;
constexpr int WO_E0A = WO_E0D + 16 * 8  * 32;
constexpr int WO_E0B = WO_E0A + 32 * 27 * 32;
constexpr int WO_E1D = WO_E0B + 32 * 27 * 32;
constexpr int WO_E1A = WO_E1D + 32 * 8  * 64;
constexpr int WO_E1B = WO_E1A + 64 * 27 * 64;
constexpr int WO_D0U = WO_E1B + 64 * 27 * 64;
constexpr int WO_D0A = WO_D0U + 64 * 8  * 32;
constexpr int WO_D0B = WO_D0A + 64 * 27 * 64;
constexpr int WO_D1U = WO_D0B + 64 * 27 * 32;
constexpr int WO_D1A = WO_D1U + 32 * 8  * 16;
constexpr int WO_D1B = WO_D1A + 32 * 27 * 32;
constexpr int WO_OA  = WO_D1B + 32 * 27 * 16;
constexpr int WO_OB  = WO_OA  + 16 * 27 * 16;
constexpr int SCRATCH_TOTAL = WO_OB + 16 * 27 * 8;

// sorted-list build: 1024-voxel chunks
constexpr int CH0 = (V0 + 1023) / 1024;
constexpr int CH1 = (V1 + 1023) / 1024;
constexpr int CH2 = (V2 + 1023) / 1024;
constexpr int CHT = CH0 + CH1 + CH2;

__device__ __align__(256) float g_scratch[SCRATCH_TOTAL];  // zero-initialized
__device__ __align__(8) int g_list0[V0];
__device__ __align__(8) int g_list1[V1];
__device__ __align__(8) int g_list2[V2];
__device__ int g_cnt[4];
__device__ int g_chunkcnt[CHT];
__device__ int g_chunkoff[CHT];

// ---------------------------------------------------------------------------
// prep kernels (identical to R10)
// ---------------------------------------------------------------------------

__global__ void prep1_kernel(const float* __restrict__ x,
                             const float* __restrict__ occ,
                             float* __restrict__ out, int outn) {
    int stride = gridDim.x * blockDim.x;
    int gt = blockIdx.x * blockDim.x + threadIdx.x;
    float4 z4 = make_float4(0.f, 0.f, 0.f, 0.f);
    float4* o4 = reinterpret_cast<float4*>(out);
    for (int i = gt; i < outn / 4; i += stride) o4[i] = z4;
    for (int i = gt; i < V0; i += stride) g_scratch[OFF_XM + i] = x[i] * occ[i];
    for (int i = gt; i < V1; i += stride) {
        int xx = i % D1, yy = (i / D1) % D1, zz = i / (D1 * D1);
        float m = 0.f;
        #pragma unroll
        for (int dz = 0; dz < 2; dz++)
            #pragma unroll
            for (int dy = 0; dy < 2; dy++)
                #pragma unroll
                for (int dx = 0; dx < 2; dx++)
                    m = fmaxf(m, occ[((2 * zz + dz) * D0 + 2 * yy + dy) * D0 + 2 * xx + dx]);
        g_scratch[OFF_M1 + i] = m;
    }
    for (int i = gt; i < V2; i += stride) {
        int xx = i % D2, yy = (i / D2) % D2, zz = i / (D2 * D2);
        float m = 0.f;
        for (int dz = 0; dz < 4; dz++)
            for (int dy = 0; dy < 4; dy++)
                #pragma unroll
                for (int dx = 0; dx < 4; dx++)
                    m = fmaxf(m, occ[((4 * zz + dz) * D0 + 4 * yy + dy) * D0 + 4 * xx + dx]);
        g_scratch[OFF_M2 + i] = m;
    }
    for (int i = gt; i < CHT; i += stride) g_chunkcnt[i] = 0;
}

__global__ void count_kernel(const float* __restrict__ occ) {
    const float* mask; int n, cbase;
    if (blockIdx.y == 0)      { mask = occ;                n = V0; cbase = 0; }
    else if (blockIdx.y == 1) { mask = g_scratch + OFF_M1; n = V1; cbase = CH0; }
    else                      { mask = g_scratch + OFF_M2; n = V2; cbase = CH0 + CH1; }
    int chunk = blockIdx.x;
    long base = (long)chunk * 1024;
    if (base >= n) return;
    int cnt = 0;
    #pragma unroll
    for (int r = 0; r < 4; r++) {
        long i = base + r * 256 + threadIdx.x;
        if (i < n && mask[i] > 0.5f) cnt++;
    }
    #pragma unroll
    for (int s = 16; s > 0; s >>= 1) cnt += __shfl_down_sync(0xffffffffu, cnt, s);
    if ((threadIdx.x & 31) == 0 && cnt) atomicAdd(&g_chunkcnt[cbase + chunk], cnt);
}

__global__ void scan_kernel() {
    __shared__ int s[1024];
    int t = threadIdx.x;
    int segBase[3] = {0, CH0, CH0 + CH1};
    int segCnt[3]  = {CH0, CH1, CH2};
    for (int seg = 0; seg < 3; seg++) {
        int val = (t < segCnt[seg]) ? g_chunkcnt[segBase[seg] + t] : 0;
        s[t] = val;
        __syncthreads();
        for (int d = 1; d < 1024; d <<= 1) {
            int add = (t >= d) ? s[t - d] : 0;
            __syncthreads();
            s[t] += add;
            __syncthreads();
        }
        if (t < segCnt[seg]) g_chunkoff[segBase[seg] + t] = s[t] - val;
        if (t == segCnt[seg] - 1) g_cnt[seg] = s[t];
        __syncthreads();
    }
}

__global__ void scatter_kernel(const float* __restrict__ occ) {
    const float* mask; int n, cbase; int* list;
    if (blockIdx.y == 0)      { mask = occ;                n = V0; cbase = 0;        list = g_list0; }
    else if (blockIdx.y == 1) { mask = g_scratch + OFF_M1; n = V1; cbase = CH0;      list = g_list1; }
    else                      { mask = g_scratch + OFF_M2; n = V2; cbase = CH0+CH1;  list = g_list2; }
    int chunk = blockIdx.x;
    long cb = (long)chunk * 1024;
    if (cb >= n) return;
    int lane = threadIdx.x & 31;
    int base = g_chunkoff[cbase + chunk];
    for (int r = 0; r < 32; r++) {
        long i = cb + r * 32 + lane;
        bool pred = (i < n) && (mask[i] > 0.5f);
        unsigned bal = __ballot_sync(0xffffffffu, pred);
        if (pred) list[base + __popc(bal & ((1u << lane) - 1))] = (int)i;
        base += __popc(bal);
    }
}

struct WPtrs { const float* p[15]; };
__device__ const int TW_DIMS[15][4] = {
    {16, 1, 27, 16}, {32, 16, 8, 32}, {32, 32, 27, 32}, {32, 32, 27, 32},
    {64, 32, 8, 64}, {64, 64, 27, 64}, {64, 64, 27, 64}, {32, 64, 8, 32},
    {64, 64, 27, 64}, {32, 64, 27, 32}, {16, 32, 8, 16}, {32, 32, 27, 32},
    {16, 32, 27, 16}, {16, 16, 27, 16}, {5, 16, 27, 8}};
__device__ const int TW_OFF[15] = {
    WO_IN, WO_E0D, WO_E0A, WO_E0B, WO_E1D, WO_E1A, WO_E1B, WO_D0U,
    WO_D0A, WO_D0B, WO_D1U, WO_D1A, WO_D1B, WO_OA, WO_OB};

__global__ void tw_kernel(WPtrs wp) {
    int e = blockIdx.y;
    int Cout = TW_DIMS[e][0], Cin = TW_DIMS[e][1], K3 = TW_DIMS[e][2], Copad = TW_DIMS[e][3];
    const float* w = wp.p[e];
    float* wt = g_scratch + TW_OFF[e];
    int total = Cin * K3 * Copad;
    for (int i = blockIdx.x * blockDim.x + threadIdx.x; i < total;
         i += gridDim.x * blockDim.x) {
        int o = i % Copad;
        int r = i / Copad;
        int ci = r / K3, t = r % K3;
        wt[i] = (o < Cout) ? w[(o * Cin + ci) * K3 + t] : 0.f;
    }
}

// ---------------------------------------------------------------------------
// conv3 inner helpers
// ---------------------------------------------------------------------------

__device__ __forceinline__ void fma16(float4& a0, float4& a0h, float4& a1, float4& a1h,
                                      float a, float b, const float* __restrict__ wp) {
    float4 wl = *reinterpret_cast<const float4*>(wp);
    float4 wh = *reinterpret_cast<const float4*>(wp + 4);
    a0.x += a * wl.x; a0.y += a * wl.y; a0.z += a * wl.z; a0.w += a * wl.w;
    a0h.x += a * wh.x; a0h.y += a * wh.y; a0h.z += a * wh.z; a0h.w += a * wh.w;
    a1.x += b * wl.x; a1.y += b * wl.y; a1.z += b * wl.z; a1.w += b * wl.w;
    a1h.x += b * wh.x; a1h.y += b * wh.y; a1h.z += b * wh.z; a1h.w += b * wh.w;
}

// batched ci-loop for one (tap, input buffer): chunks of 4 channels,
// 8 input LDGs issued back-to-back before the FMA blocks.
template <int CIN, int COPAD>
__device__ __forceinline__ void ci_loop(float4& a0, float4& a0h, float4& a1, float4& a1h,
                                        const float* ip0, const float* ip1,
                                        bool k0, bool k1, int vol,
                                        const float*& wp) {
    if (CIN % 4 == 0) {
        #pragma unroll
        for (int ci = 0; ci < CIN; ci += 4) {
            float av[4], bv[4];
            #pragma unroll
            for (int j = 0; j < 4; j++) {
                av[j] = k0 ? __ldg(ip0) : 0.f; ip0 += vol;
                bv[j] = k1 ? __ldg(ip1) : 0.f; ip1 += vol;
            }
            #pragma unroll
            for (int j = 0; j < 4; j++) {
                fma16(a0, a0h, a1, a1h, av[j], bv[j], wp);
                wp += 27 * COPAD;
            }
        }
    } else {
        #pragma unroll
        for (int ci = 0; ci < CIN; ci++) {
            float a = k0 ? __ldg(ip0) : 0.f; ip0 += vol;
            float b = k1 ? __ldg(ip1) : 0.f; ip1 += vol;
            fma16(a0, a0h, a1, a1h, a, b, wp);
            wp += 27 * COPAD;
        }
    }
}

// ---------------------------------------------------------------------------
// conv3: voxel-pair x 8-cout gather conv (R10 structure + batched loads)
// ---------------------------------------------------------------------------

template <int CINA, int CINB, int COUT, int COPAD, bool RELU>
__global__ __launch_bounds__(256)
void conv3_pair8(const float* __restrict__ inA, const float* __restrict__ inB,
                 const float* __restrict__ wt, float* __restrict__ out,
                 const int* __restrict__ list, const int* __restrict__ cnt,
                 int cntIdx, int D) {
    const int vol = D * D * D;
    const int CG = COPAD / 8;
    int n = cnt[cntIdx];
    int npair = (n + 1) >> 1;
    int total = npair * CG;
    for (int w = blockIdx.x * blockDim.x + threadIdx.x; w < total;
         w += gridDim.x * blockDim.x) {
        int pi = w / CG;
        int cg = w % CG;
        int i0 = 2 * pi;
        bool has1 = (i0 + 1) < n;
        int2 vp = *reinterpret_cast<const int2*>(list + i0);
        int v0 = vp.x;
        int v1 = has1 ? vp.y : v0;
        int x0 = v0 % D, y0 = (v0 / D) % D, z0 = v0 / (D * D);
        int x1 = v1 % D, y1 = (v1 / D) % D, z1 = v1 / (D * D);
        float4 a0 = make_float4(0.f, 0.f, 0.f, 0.f);
        float4 a0h = make_float4(0.f, 0.f, 0.f, 0.f);
        float4 a1 = make_float4(0.f, 0.f, 0.f, 0.f);
        float4 a1h = make_float4(0.f, 0.f, 0.f, 0.f);
        for (int dz = -1; dz <= 1; dz++) {
            int zz0 = z0 + dz, zz1 = z1 + dz;
            bool zk0 = (unsigned)zz0 < (unsigned)D;
            bool zk1 = (unsigned)zz1 < (unsigned)D;
            if (!zk0 && !zk1) continue;
            for (int dy = -1; dy <= 1; dy++) {
                int yy0 = y0 + dy, yy1 = y1 + dy;
                bool yk0 = zk0 && ((unsigned)yy0 < (unsigned)D);
                bool yk1 = zk1 && ((unsigned)yy1 < (unsigned)D);
                if (!yk0 && !yk1) continue;
                for (int dx = -1; dx <= 1; dx++) {
                    int xx0 = x0 + dx, xx1 = x1 + dx;
                    bool k0 = yk0 && ((unsigned)xx0 < (unsigned)D);
                    bool k1 = yk1 && ((unsigned)xx1 < (unsigned)D);
                    if (!k0 && !k1) continue;
                    int t = ((dz + 1) * 3 + (dy + 1)) * 3 + (dx + 1);
                    int noff0 = k0 ? (zz0 * D + yy0) * D + xx0 : 0;
                    int noff1 = k1 ? (zz1 * D + yy1) * D + xx1 : 0;
                    const float* wp = wt + t * COPAD + cg * 8;
                    ci_loop<CINA, COPAD>(a0, a0h, a1, a1h,
                                         inA + noff0, inA + noff1, k0, k1, vol, wp);
                    if (CINB > 0)
                        ci_loop<(CINB > 0 ? CINB : 4), COPAD>(
                            a0, a0h, a1, a1h,
                            inB + noff0, inB + noff1, k0, k1, vol, wp);
                }
            }
        }
        if (RELU) {
            a0.x = fmaxf(a0.x, 0.f); a0.y = fmaxf(a0.y, 0.f);
            a0.z = fmaxf(a0.z, 0.f); a0.w = fmaxf(a0.w, 0.f);
            a0h.x = fmaxf(a0h.x, 0.f); a0h.y = fmaxf(a0h.y, 0.f);
            a0h.z = fmaxf(a0h.z, 0.f); a0h.w = fmaxf(a0h.w, 0.f);
            a1.x = fmaxf(a1.x, 0.f); a1.y = fmaxf(a1.y, 0.f);
            a1.z = fmaxf(a1.z, 0.f); a1.w = fmaxf(a1.w, 0.f);
            a1h.x = fmaxf(a1h.x, 0.f); a1h.y = fmaxf(a1h.y, 0.f);
            a1h.z = fmaxf(a1h.z, 0.f); a1h.w = fmaxf(a1h.w, 0.f);
        }
        int co = cg * 8;
        float r0[8] = {a0.x, a0.y, a0.z, a0.w, a0h.x, a0h.y, a0h.z, a0h.w};
        float r1[8] = {a1.x, a1.y, a1.z, a1.w, a1h.x, a1h.y, a1h.z, a1h.w};
        #pragma unroll
        for (int k = 0; k < 8; k++)
            if (co + k < COUT) out[(co + k) * vol + v0] = r0[k];
        if (has1) {
            #pragma unroll
            for (int k = 0; k < 8; k++)
                if (co + k < COUT) out[(co + k) * vol + v1] = r1[k];
        }
    }
}

// ---------------------------------------------------------------------------
// down2: voxel-pair tiling (unchanged from R10)
// ---------------------------------------------------------------------------

template <int CIN, int COUT, int COPAD>
__global__ __launch_bounds__(256)
void down2_pair(const float* __restrict__ in, const float* __restrict__ wt,
                float* __restrict__ out, const int* __restrict__ list,
                const int* __restrict__ cnt, int cntIdx, int Dc) {
    const int Df = Dc * 2;
    const int volf = Df * Df * Df;
    const int volc = Dc * Dc * Dc;
    const int CG = COPAD / 4;
    int n = cnt[cntIdx];
    int npair = (n + 1) >> 1;
    int total = npair * CG;
    for (int w = blockIdx.x * blockDim.x + threadIdx.x; w < total;
         w += gridDim.x * blockDim.x) {
        int pi = w / CG;
        int cg = w % CG;
        int i0 = 2 * pi;
        bool has1 = (i0 + 1) < n;
        int2 vp = *reinterpret_cast<const int2*>(list + i0);
        int v0 = vp.x;
        int v1 = has1 ? vp.y : v0;
        int x0 = v0 % Dc, y0 = (v0 / Dc) % Dc, z0 = v0 / (Dc * Dc);
        int x1 = v1 % Dc, y1 = (v1 / Dc) % Dc, z1 = v1 / (Dc * Dc);
        float4 acc0 = make_float4(0.f, 0.f, 0.f, 0.f);
        float4 acc1 = make_float4(0.f, 0.f, 0.f, 0.f);
        #pragma unroll
        for (int t = 0; t < 8; t++) {
            int tz = t >> 2, ty = (t >> 1) & 1, tx = t & 1;
            int noff0 = ((2 * z0 + tz) * Df + (2 * y0 + ty)) * Df + (2 * x0 + tx);
            int noff1 = ((2 * z1 + tz) * Df + (2 * y1 + ty)) * Df + (2 * x1 + tx);
            const float* ip0 = in + noff0;
            const float* ip1 = in + noff1;
            const float* wp = wt + t * COPAD + cg * 4;
            #pragma unroll
            for (int ci = 0; ci < CIN; ci++) {
                float a = __ldg(ip0); ip0 += volf;
                float b = __ldg(ip1); ip1 += volf;
                float4 wv = *reinterpret_cast<const float4*>(wp);
                wp += 8 * COPAD;
                acc0.x += a * wv.x; acc0.y += a * wv.y;
                acc0.z += a * wv.z; acc0.w += a * wv.w;
                acc1.x += b * wv.x; acc1.y += b * wv.y;
                acc1.z += b * wv.z; acc1.w += b * wv.w;
            }
        }
        int co = cg * 4;
        out[(co + 0) * volc + v0] = acc0.x;
        out[(co + 1) * volc + v0] = acc0.y;
        out[(co + 2) * volc + v0] = acc0.z;
        out[(co + 3) * volc + v0] = acc0.w;
        if (has1) {
            out[(co + 0) * volc + v1] = acc1.x;
            out[(co + 1) * volc + v1] = acc1.y;
            out[(co + 2) * volc + v1] = acc1.z;
            out[(co + 3) * volc + v1] = acc1.w;
        }
    }
}

// ---------------------------------------------------------------------------
// up2 (unchanged)
// ---------------------------------------------------------------------------

template <int CIN, int COUT, int COPAD>
__global__ __launch_bounds__(256)
void up2_kernel(const float* __restrict__ in, const float* __restrict__ wt,
                float* __restrict__ out, const int* __restrict__ list,
                const int* __restrict__ cnt, int cntIdx, int Df) {
    const int Dc = Df / 2;
    const int volf = Df * Df * Df;
    const int volc = Dc * Dc * Dc;
    const int CG = COPAD / 4;
    int n = cnt[cntIdx];
    int total = n * CG;
    for (int w = blockIdx.x * blockDim.x + threadIdx.x; w < total;
         w += gridDim.x * blockDim.x) {
        int v = list[w / CG];
        int cg = w % CG;
        int x0 = v % Df, y0 = (v / Df) % Df, z0 = v / (Df * Df);
        int t = ((1 - (z0 & 1)) * 2 + (1 - (y0 & 1))) * 2 + (1 - (x0 & 1));
        int coff = ((z0 >> 1) * Dc + (y0 >> 1)) * Dc + (x0 >> 1);
        float4 acc = make_float4(0.f, 0.f, 0.f, 0.f);
        const float* ip = in + coff;
        const float* wp = wt + t * COPAD + cg * 4;
        #pragma unroll
        for (int ci = 0; ci < CIN; ci++) {
            float iv = __ldg(ip); ip += volc;
            float4 wv = *reinterpret_cast<const float4*>(wp);
            wp += 8 * COPAD;
            acc.x += iv * wv.x; acc.y += iv * wv.y;
            acc.z += iv * wv.z; acc.w += iv * wv.w;
        }
        int co = cg * 4;
        out[(co + 0) * volf + v] = acc.x;
        out[(co + 1) * volf + v] = acc.y;
        out[(co + 2) * volf + v] = acc.z;
        out[(co + 3) * volf + v] = acc.w;
    }
}

// ---------------------------------------------------------------------------
// launch
// ---------------------------------------------------------------------------

extern "C" void kernel_launch(void* const* d_in, const int* in_sizes, int n_in,
                              void* d_out, int out_size) {
    (void)in_sizes; (void)n_in;
    const float* x   = (const float*)d_in[0];
    const float* occ = (const float*)d_in[1];
    float* out = (float*)d_out;

    float* SB = nullptr;
    int *L0 = nullptr, *L1 = nullptr, *L2 = nullptr, *CNT = nullptr;
    cudaGetSymbolAddress((void**)&SB,  g_scratch);
    cudaGetSymbolAddress((void**)&L0,  g_list0);
    cudaGetSymbolAddress((void**)&L1,  g_list1);
    cudaGetSymbolAddress((void**)&L2,  g_list2);
    cudaGetSymbolAddress((void**)&CNT, g_cnt);

    const int NT = 256;
    const int NB = 2048;

    prep1_kernel<<<1024, NT>>>(x, occ, out, out_size);
    count_kernel<<<dim3(CH0, 3), NT>>>(occ);
    scan_kernel<<<1, 1024>>>();
    scatter_kernel<<<dim3(CH0, 3), 32>>>(occ);
    WPtrs wp;
    for (int i = 0; i < 15; i++) wp.p[i] = (const float*)d_in[2 + i];
    tw_kernel<<<dim3(216, 15), NT>>>(wp);

    // U-Net pipeline (channel-major features)
    conv3_pair8<1, 0, 16, 16, false><<<NB, NT>>>(
        SB + OFF_XM, nullptr, SB + WO_IN, SB + OFF_SKIP0, L0, CNT, 0, D0);

    // encoder level 0
    down2_pair<16, 32, 32><<<NB, NT>>>(
        SB + OFF_SKIP0, SB + WO_E0D, SB + OFF_HA, L1, CNT, 1, D1);
    conv3_pair8<32, 0, 32, 32, true><<<NB, NT>>>(
        SB + OFF_HA, nullptr, SB + WO_E0A, SB + OFF_HB, L1, CNT, 1, D1);
    conv3_pair8<32, 0, 32, 32, false><<<NB, NT>>>(
        SB + OFF_HB, nullptr, SB + WO_E0B, SB + OFF_S1, L1, CNT, 1, D1);

    // encoder level 1
    down2_pair<32, 64, 64><<<NB, NT>>>(
        SB + OFF_S1, SB + WO_E1D, SB + OFF_CA, L2, CNT, 2, D2);
    conv3_pair8<64, 0, 64, 64, true><<<NB, NT>>>(
        SB + OFF_CA, nullptr, SB + WO_E1A, SB + OFF_CB, L2, CNT, 2, D2);
    conv3_pair8<64, 0, 64, 64, false><<<NB, NT>>>(
        SB + OFF_CB, nullptr, SB + WO_E1B, SB + OFF_CA, L2, CNT, 2, D2);

    // decoder stage 0 (to level 1)
    up2_kernel<64, 32, 32><<<NB, NT>>>(
        SB + OFF_CA, SB + WO_D0U, SB + OFF_HA, L1, CNT, 1, D1);
    conv3_pair8<32, 32, 64, 64, true><<<NB, NT>>>(
        SB + OFF_HA, SB + OFF_S1, SB + WO_D0A, SB + OFF_H64, L1, CNT, 1, D1);
    conv3_pair8<64, 0, 32, 32, false><<<NB, NT>>>(
        SB + OFF_H64, nullptr, SB + WO_D0B, SB + OFF_HB, L1, CNT, 1, D1);

    // decoder stage 1 (to level 0)
    up2_kernel<32, 16, 16><<<NB, NT>>>(
        SB + OFF_HB, SB + WO_D1U, SB + OFF_UP1, L0, CNT, 0, D0);
    conv3_pair8<16, 16, 32, 32, true><<<NB, NT>>>(
        SB + OFF_UP1, SB + OFF_SKIP0, SB + WO_D1A, SB + OFF_T32, L0, CNT, 0, D0);
    conv3_pair8<32, 0, 16, 16, false><<<NB, NT>>>(
        SB + OFF_T32, nullptr, SB + WO_D1B, SB + OFF_UP1, L0, CNT, 0, D0);

    // output block
    conv3_pair8<16, 0, 16, 16, true><<<NB, NT>>>(
        SB + OFF_UP1, nullptr, SB + WO_OA, SB + OFF_SKIP0, L0, CNT, 0, D0);
    conv3_pair8<16, 0, 5, 8, false><<<NB, NT>>>(
        SB + OFF_SKIP0, nullptr, SB + WO_OB, out, L0, CNT, 0, D0);
}